// round 12
// baseline (speedup 1.0000x reference)
#include <cuda_runtime.h>
#include <cuda_bf16.h>
#include <cstdint>

// Problem constants: T=32768, E=256, K=8, D=8, r=2
#define E_EXPERTS 256
#define D_DEVS    8
#define K_TOPK    8
#define E_PER_DEV (E_EXPERTS / D_DEVS)   // 32
#define TOK_PER_BLK 32                   // 8 warps x 4 tokens

// R8 structure (best so far) + L2 evict_last cache hints to keep the
// steady-state working set (33MB out + 32MB topk) resident in the 126MB L2,
// eliminating per-replay DRAM writeback churn.
__global__ __launch_bounds__(256) void moe_remap_resident(
    const float* __restrict__ topk,     // [T, E]
    const int*   __restrict__ mapping,  // [E, D] one-hot
    const int*   __restrict__ meta,     // [T, K]
    float*       __restrict__ out,      // [D, T, 32]
    float*       __restrict__ mask,     // [T/2, D]
    int T)
{
    __shared__ __align__(128) float sdata[D_DEVS * TOK_PER_BLK * E_PER_DEV]; // 32KB
    __shared__ int wcnt_s[64];
    __shared__ int C_s[64];
    __shared__ short invperm_s[E_EXPERTS];

    const int tid  = threadIdx.x;
    const int lane = tid & 31;
    const int warp = tid >> 5;
    const int quad = blockIdx.x * 8 + warp;      // 4-token group
    const int t0   = quad << 2;
    const int blkT = blockIdx.x * TOK_PER_BLK;

    // L2 policy: keep lines resident (evict_last)
    uint64_t pol;
    asm("createpolicy.fractional.L2::evict_last.b64 %0, 1.0;" : "=l"(pol));

    // ---- independent loads first ----
    const int e = meta[t0 * K_TOPK + lane];      // coalesced

    const int4 a4 = reinterpret_cast<const int4*>(mapping)[tid * 2];
    const int4 b4 = reinterpret_cast<const int4*>(mapping)[tid * 2 + 1];

    // gather with evict_last (topk stays L2-resident across replays)
    const int tl = lane >> 3;                                // local token 0..3
    float gv;
    asm volatile("ld.global.nc.L2::cache_hint.f32 %0, [%1], %2;"
                 : "=f"(gv)
                 : "l"(topk + (t0 + tl) * E_EXPERTS + e), "l"(pol));

    // ---- invperm: argmax + ballot counts ----
    int v8[8] = {a4.x, a4.y, a4.z, a4.w, b4.x, b4.y, b4.z, b4.w};
    int best = v8[0], d = 0;
#pragma unroll
    for (int i = 1; i < D_DEVS; i++)
        if (v8[i] > best) { best = v8[i]; d = i; }           // first max wins

    const unsigned lt = (1u << lane) - 1u;
    int within = 0, mycnt = 0;
#pragma unroll
    for (int d2 = 0; d2 < D_DEVS; d2++) {
        unsigned b = __ballot_sync(0xffffffffu, d == d2);
        if (d2 == d)    within = __popc(b & lt);
        if (lane == d2) mycnt  = __popc(b);
    }
    if (lane < D_DEVS) wcnt_s[warp * 8 + lane] = mycnt;

    // ---- zero 32KB tile: 8 x STS.128 per thread ----
    {
        float4* s4 = reinterpret_cast<float4*>(sdata);
        const float4 z = make_float4(0.f, 0.f, 0.f, 0.f);
#pragma unroll
        for (int i = 0; i < 8; i++) s4[tid + 256 * i] = z;
    }
    __syncthreads();

    // ---- warp 0: exclusive scan of 64 counts, order f = d*8 + w ----
    if (warp == 0) {
        int x0 = wcnt_s[(lane & 7) * 8 + (lane >> 3)];
        int x1 = wcnt_s[((lane + 32) & 7) * 8 + ((lane + 32) >> 3)];
        int i0 = x0, i1 = x1;
#pragma unroll
        for (int o = 1; o < 32; o <<= 1) {
            int y0 = __shfl_up_sync(0xffffffffu, i0, o);
            int y1 = __shfl_up_sync(0xffffffffu, i1, o);
            if (lane >= o) { i0 += y0; i1 += y1; }
        }
        const int tot0 = __shfl_sync(0xffffffffu, i0, 31);
        C_s[lane]      = i0 - x0;
        C_s[lane + 32] = i1 - x1 + tot0;
    }
    __syncthreads();
    invperm_s[tid] = (short)(C_s[d * 8 + warp] + within);
    __syncthreads();

    // ---- scatter into smem ----
    const int p  = invperm_s[e];
    const int ds = p >> 5, js = p & 31;
    sdata[ds * (TOK_PER_BLK * E_PER_DEV) + (warp * 4 + tl) * E_PER_DEV + js] = gv;

    // ---- pair masks ----
    {
        const unsigned pm = (lane < 16) ? 0x0000ffffu : 0xffff0000u;
        const unsigned r  = __reduce_or_sync(pm, 1u << ds);
        const unsigned hr = __shfl_sync(0xffffffffu, r, 16);
        if (lane < 16) {
            const unsigned bits = (lane < 8) ? r : hr;
            const float mv = ((bits >> (lane & 7)) & 1u) ? 1.0f : 0.0f;
            asm volatile("st.global.L2::cache_hint.f32 [%0], %1, %2;"
                         :: "l"(mask + quad * 16 + lane), "f"(mv), "l"(pol)
                         : "memory");
        }
    }

    // ---- publish smem to async proxy; bulk-store 8 x 4KB plane slices ----
    asm volatile("fence.proxy.async.shared::cta;" ::: "memory");
    __syncthreads();

    if (tid == 0) {
        uint32_t saddr;
        asm("{ .reg .u64 t; cvta.to.shared.u64 t, %1; cvt.u32.u64 %0, t; }"
            : "=r"(saddr) : "l"(sdata));
#pragma unroll
        for (int dd = 0; dd < D_DEVS; dd++) {
            float* gdst = out + dd * (T * E_PER_DEV) + blkT * E_PER_DEV;
            asm volatile(
                "cp.async.bulk.global.shared::cta.bulk_group.L2::cache_hint "
                "[%0], [%1], %2, %3;"
                :: "l"(gdst),
                   "r"(saddr + dd * (TOK_PER_BLK * E_PER_DEV * 4)),
                   "r"(TOK_PER_BLK * E_PER_DEV * 4),
                   "l"(pol)
                : "memory");
        }
        asm volatile("cp.async.bulk.commit_group;" ::: "memory");
        // hold CTA only until TMA has READ smem; writes drain async in L2
        asm volatile("cp.async.bulk.wait_group.read 0;" ::: "memory");
    }
}

extern "C" void kernel_launch(void* const* d_in, const int* in_sizes, int n_in,
                              void* d_out, int out_size) {
    const float* topk    = (const float*)d_in[0];   // [1,1,T,E]
    const int*   mapping = (const int*)  d_in[1];   // [1,1,E,D]
    const int*   meta    = (const int*)  d_in[2];   // [1,1,T,K]

    const int T = in_sizes[0] / E_EXPERTS;          // 32768

    float* out  = (float*)d_out;                            // [D, T, 32]
    float* mask = out + (size_t)D_DEVS * T * E_PER_DEV;     // [T/2, D]

    const int blocks = T / TOK_PER_BLK;             // 1024
    moe_remap_resident<<<blocks, 256>>>(topk, mapping, meta, out, mask, T);
}

// round 13
// speedup vs baseline: 1.1905x; 1.1905x over previous
#include <cuda_runtime.h>
#include <cuda_bf16.h>
#include <cstdint>

// Problem constants: T=32768, E=256, K=8, D=8, r=2
#define E_EXPERTS 256
#define D_DEVS    8
#define K_TOPK    8
#define E_PER_DEV (E_EXPERTS / D_DEVS)   // 32
#define TOK_PER_TILE 32
#define TILE_FLOATS (D_DEVS * TOK_PER_TILE * E_PER_DEV)   // 8192 floats = 32KB
#define NTILES 1024                       // T / TOK_PER_TILE
#define GRID 296                          // 2 blocks/SM persistent

// Persistent double-buffered build + TMA-out pipeline.
__global__ __launch_bounds__(256, 2) void moe_remap_pers(
    const float* __restrict__ topk,     // [T, E]
    const int*   __restrict__ mapping,  // [E, D] one-hot
    const int*   __restrict__ meta,     // [T, K]
    float*       __restrict__ out,      // [D, T, 32]
    float*       __restrict__ mask,     // [T/2, D]
    int T)
{
    extern __shared__ __align__(128) float sdata[];   // 2 * 32KB
    __shared__ int wcnt_s[64];
    __shared__ int C_s[64];
    __shared__ short invperm_s[E_EXPERTS];

    const int tid  = threadIdx.x;
    const int lane = tid & 31;
    const int warp = tid >> 5;
    const int tl   = lane >> 3;                  // local token 0..3

    // ---------- prologue loads for first tile ----------
    int tile = blockIdx.x;
    int e_c = 0; float gv_c = 0.f;
    {
        const int t0 = tile * TOK_PER_TILE + warp * 4;
        e_c  = meta[t0 * K_TOPK + lane];
        gv_c = topk[(t0 + tl) * E_EXPERTS + e_c];
    }

    // ---------- invperm (once per block) ----------
    {
        const int4 a4 = reinterpret_cast<const int4*>(mapping)[tid * 2];
        const int4 b4 = reinterpret_cast<const int4*>(mapping)[tid * 2 + 1];
        int v8[8] = {a4.x, a4.y, a4.z, a4.w, b4.x, b4.y, b4.z, b4.w};
        int best = v8[0], d = 0;
#pragma unroll
        for (int i = 1; i < D_DEVS; i++)
            if (v8[i] > best) { best = v8[i]; d = i; }   // first max wins

        const unsigned lt = (1u << lane) - 1u;
        int within = 0, mycnt = 0;
#pragma unroll
        for (int d2 = 0; d2 < D_DEVS; d2++) {
            unsigned b = __ballot_sync(0xffffffffu, d == d2);
            if (d2 == d)    within = __popc(b & lt);
            if (lane == d2) mycnt  = __popc(b);
        }
        if (lane < D_DEVS) wcnt_s[warp * 8 + lane] = mycnt;

        // full zero of BOTH buffers (once): 4096 f4 / 256 thr = 16 each
        {
            float4* s4 = reinterpret_cast<float4*>(sdata);
            const float4 z = make_float4(0.f, 0.f, 0.f, 0.f);
#pragma unroll
            for (int i = 0; i < 16; i++) s4[tid + 256 * i] = z;
        }
        __syncthreads();

        if (warp == 0) {
            int x0 = wcnt_s[(lane & 7) * 8 + (lane >> 3)];
            int x1 = wcnt_s[((lane + 32) & 7) * 8 + ((lane + 32) >> 3)];
            int i0 = x0, i1 = x1;
#pragma unroll
            for (int o = 1; o < 32; o <<= 1) {
                int y0 = __shfl_up_sync(0xffffffffu, i0, o);
                int y1 = __shfl_up_sync(0xffffffffu, i1, o);
                if (lane >= o) { i0 += y0; i1 += y1; }
            }
            const int tot0 = __shfl_sync(0xffffffffu, i0, 31);
            C_s[lane]      = i0 - x0;
            C_s[lane + 32] = i1 - x1 + tot0;
        }
        __syncthreads();
        invperm_s[tid] = (short)(C_s[d * 8 + warp] + within);
        __syncthreads();
    }

    uint32_t sbase;
    asm("{ .reg .u64 t; cvta.to.shared.u64 t, %1; cvt.u32.u64 %0, t; }"
        : "=r"(sbase) : "l"(sdata));

    // ---------- pipeline over tiles ----------
    int pos[2] = {-1, -1};       // this thread's last scatter pos per buffer
    int parity = 0;

    while (tile < NTILES) {
        // prefetch next tile's loads (hidden under this tile's port work)
        const int ntile = tile + GRID;
        int e_n = 0; float gv_n = 0.f;
        if (ntile < NTILES) {
            const int t0n = ntile * TOK_PER_TILE + warp * 4;
            e_n  = meta[t0n * K_TOPK + lane];
            gv_n = topk[(t0n + tl) * E_EXPERTS + e_n];
        }

        float* buf = sdata + parity * TILE_FLOATS;

        // buffer free? (group from 2 tiles ago must have been READ)
        if (tid == 0)
            asm volatile("cp.async.bulk.wait_group.read 1;" ::: "memory");
        __syncthreads();

        // spot re-zero previous scatter positions in this buffer
        if (pos[parity] >= 0) buf[pos[parity]] = 0.f;
        __syncthreads();        // zeros ordered before new scatters

        // scatter this tile's selections
        const int p  = invperm_s[e_c];
        const int ds = p >> 5, js = p & 31;
        const int position = ds * (TOK_PER_TILE * E_PER_DEV)
                           + (warp * 4 + tl) * E_PER_DEV + js;
        buf[position] = gv_c;
        pos[parity] = position;

        // mask rows (pairs 2q, 2q+1 of quad = tile*8 + warp)
        {
            const unsigned pm = (lane < 16) ? 0x0000ffffu : 0xffff0000u;
            const unsigned r  = __reduce_or_sync(pm, 1u << ds);
            const unsigned hr = __shfl_sync(0xffffffffu, r, 16);
            if (lane < 16) {
                const unsigned bits = (lane < 8) ? r : hr;
                mask[(tile * 8 + warp) * 16 + lane] =
                    ((bits >> (lane & 7)) & 1u) ? 1.0f : 0.0f;
            }
        }

        asm volatile("fence.proxy.async.shared::cta;" ::: "memory");
        __syncthreads();

        if (tid == 0) {
            const uint32_t saddr = sbase + parity * (TILE_FLOATS * 4);
            const int blkT = tile * TOK_PER_TILE;
#pragma unroll
            for (int dd = 0; dd < D_DEVS; dd++) {
                float* gdst = out + dd * (T * E_PER_DEV) + blkT * E_PER_DEV;
                asm volatile(
                    "cp.async.bulk.global.shared::cta.bulk_group [%0], [%1], %2;"
                    :: "l"(gdst),
                       "r"(saddr + dd * (TOK_PER_TILE * E_PER_DEV * 4)),
                       "r"(TOK_PER_TILE * E_PER_DEV * 4)
                    : "memory");
            }
            asm volatile("cp.async.bulk.commit_group;" ::: "memory");
        }

        // rotate pipeline
        e_c = e_n; gv_c = gv_n;
        tile = ntile;
        parity ^= 1;
    }

    // hold CTA until remaining TMA reads of smem complete (writes drain async)
    if (tid == 0)
        asm volatile("cp.async.bulk.wait_group.read 0;" ::: "memory");
    __syncthreads();
}

extern "C" void kernel_launch(void* const* d_in, const int* in_sizes, int n_in,
                              void* d_out, int out_size) {
    const float* topk    = (const float*)d_in[0];   // [1,1,T,E]
    const int*   mapping = (const int*)  d_in[1];   // [1,1,E,D]
    const int*   meta    = (const int*)  d_in[2];   // [1,1,T,K]

    const int T = in_sizes[0] / E_EXPERTS;          // 32768

    float* out  = (float*)d_out;                            // [D, T, 32]
    float* mask = out + (size_t)D_DEVS * T * E_PER_DEV;     // [T/2, D]

    const int smem = 2 * TILE_FLOATS * 4;           // 64KB dynamic
    cudaFuncSetAttribute(moe_remap_pers,
                         cudaFuncAttributeMaxDynamicSharedMemorySize, smem);
    moe_remap_pers<<<GRID, 256, smem>>>(topk, mapping, meta, out, mask, T);
}